// round 7
// baseline (speedup 1.0000x reference)
#include <cuda_runtime.h>
#include <cstdint>

#define EV 50000
#define EDIM 128
#define HDIM 64
#define GDIM 256
#define BSZ 512
#define SLEN 512
#define NB 4
typedef unsigned long long ull;

__device__ float g_xproj[(size_t)BSZ * SLEN * GDIM];

__device__ __forceinline__ uint32_t smem_u32(const void* p) {
    uint32_t a;
    asm("{ .reg .u64 t; cvta.to.shared.u64 t, %1; cvt.u32.u64 %0, t; }"
        : "=r"(a) : "l"(p));
    return a;
}
__device__ __forceinline__ ull fma2(ull a, ull b, ull c) {
    ull d; asm("fma.rn.f32x2 %0, %1, %2, %3;" : "=l"(d) : "l"(a), "l"(b), "l"(c));
    return d;
}
__device__ __forceinline__ void lds_2x64(ull& a, ull& b, uint32_t addr) {
    asm volatile("ld.shared.v2.u64 {%0, %1}, [%2];" : "=l"(a), "=l"(b) : "r"(addr));
}
__device__ __forceinline__ float hadd2(ull v) {
    float lo, hi; asm("mov.b64 {%0, %1}, %2;" : "=f"(lo), "=f"(hi) : "l"(v));
    return lo + hi;
}
__device__ __forceinline__ ull pack2(float lo, float hi) {
    ull d; asm("mov.b64 %0, {%1, %2};" : "=l"(d) : "f"(lo), "f"(hi));
    return d;
}
__device__ __forceinline__ float tanh_ap(float x) {
    float y; asm("tanh.approx.f32 %0, %1;" : "=f"(y) : "f"(x));
    return y;
}
__device__ __forceinline__ float sig_ap(float x) {
    return 0.5f * tanh_ap(0.5f * x) + 0.5f;
}

// ============ Kernel A: embed + x@Wih0^T + bias (unchanged, grid 148) ==========
#define KA_WPAD 132
#define KA_SMEM ((GDIM * KA_WPAD + 32 * KA_WPAD) * 4)

__global__ void __launch_bounds__(256, 1)
embed_xproj_kernel(const int* __restrict__ seq, const float* __restrict__ emb,
                   const float* __restrict__ Wih0, const float* __restrict__ bih0,
                   const float* __restrict__ bhh0) {
    extern __shared__ float sm[];
    float* Ws = sm;
    float* xs = sm + GDIM * KA_WPAD;
    const int tid = threadIdx.x;
    const int j = tid & 63, tq = tid >> 6;

    for (int i = tid; i < GDIM * 32; i += 256) {
        int g = i >> 5, k4 = i & 31;
        *(float4*)&Ws[g * KA_WPAD + k4 * 4] =
            ((const float4*)Wih0)[(size_t)g * 32 + k4];
    }
    float bias[4];
#pragma unroll
    for (int q = 0; q < 4; q++) bias[q] = bih0[q * 64 + j] + bhh0[q * 64 + j];

    uint32_t s_w[4];
#pragma unroll
    for (int q = 0; q < 4; q++)
        s_w[q] = smem_u32(Ws) + (q * 64 + j) * (KA_WPAD * 4);
    const uint32_t s_xb = smem_u32(xs) + (tq * 8) * (KA_WPAD * 4);

    const int ntiles = (BSZ * SLEN) / 32;
    const int mytok = tid >> 5, myk = tid & 31;
    float4 pf[4];

    auto ldx = [&](int tile) {
        const int base = tile * 32;
#pragma unroll
        for (int i = 0; i < 4; i++) {
            int idx = __ldg(seq + base + mytok + 8 * i);
            idx = idx < 0 ? 0 : (idx >= EV ? EV - 1 : idx);
            pf[i] = __ldg((const float4*)emb + (size_t)idx * 32 + myk);
        }
    };
    auto stx = [&]() {
#pragma unroll
        for (int i = 0; i < 4; i++)
            *(float4*)&xs[(mytok + 8 * i) * KA_WPAD + myk * 4] = pf[i];
    };

    int tile = blockIdx.x;
    if (tile < ntiles) ldx(tile);
    __syncthreads();
    if (tile < ntiles) stx();
    __syncthreads();

    for (; tile < ntiles; tile += gridDim.x) {
        const int nxt = tile + gridDim.x;
        if (nxt < ntiles) ldx(nxt);

        ull acc[4][8];
#pragma unroll
        for (int q = 0; q < 4; q++)
#pragma unroll
            for (int t = 0; t < 8; t++) acc[q][t] = 0ULL;

#pragma unroll 4
        for (int k4 = 0; k4 < 32; k4++) {
            ull w01[4], w23[4];
#pragma unroll
            for (int q = 0; q < 4; q++) lds_2x64(w01[q], w23[q], s_w[q] + k4 * 16);
#pragma unroll
            for (int t = 0; t < 8; t++) {
                ull x01, x23;
                lds_2x64(x01, x23, s_xb + t * (KA_WPAD * 4) + k4 * 16);
#pragma unroll
                for (int q = 0; q < 4; q++) {
                    acc[q][t] = fma2(w01[q], x01, acc[q][t]);
                    acc[q][t] = fma2(w23[q], x23, acc[q][t]);
                }
            }
        }
        const int gbase = tile * 32 + tq * 8;
#pragma unroll
        for (int t = 0; t < 8; t++) {
#pragma unroll
            for (int q = 0; q < 4; q++)
                g_xproj[(size_t)(gbase + t) * GDIM + q * 64 + j] =
                    hadd2(acc[q][t]) + bias[q];
        }
        __syncthreads();
        if (nxt < ntiles) stx();
        __syncthreads();
    }
}

// ============ Kernel B: 512 threads, k-split matvec, w1 halves in regs =========
#define KB_WPAD 68
// W0s [256][68] + h0s/h1s [4][64] + psA/psB [2][4][256] + b1s[256]
#define KB_SMEM ((GDIM * KB_WPAD + 2 * 256 + 2 * 2048 + 256) * 4)

__global__ void __launch_bounds__(512, 1)
lstm_rec_kernel(const float* __restrict__ Whh0, const float* __restrict__ Wih1,
                const float* __restrict__ Whh1, const float* __restrict__ bih1,
                const float* __restrict__ bhh1, const float* __restrict__ Wfc,
                const float* __restrict__ bfc, float* __restrict__ out) {
    extern __shared__ float sm[];
    float* W0s = sm;                    // [256][68]
    float* h0s = W0s + GDIM * KB_WPAD;  // [4][64]
    float* h1s = h0s + 256;             // [4][64]
    float* psA = h1s + 256;             // [2][4][256] layer0 partials
    float* psB = psA + 2048;            // [2][4][256] layer1 partials
    float* b1s = psB + 2048;            // [256]

    const int tid = threadIdx.x;
    const int r  = tid & 255;   // gate row
    const int hh = tid >> 8;    // k-half: 0 -> k[0,32), 1 -> k[32,64)
    const int cnb = r >> 6, cj = r & 63;   // cell (batch, hidden)

    for (int i = tid; i < GDIM * 16; i += 512) {
        int g = i >> 4, k4 = i & 15;
        *(float4*)&W0s[g * KB_WPAD + k4 * 4] = ((const float4*)Whh0)[i];
    }
    if (tid < 256) {
        h0s[tid] = 0.0f;
        h1s[tid] = 0.0f;
        b1s[tid] = bih1[tid] + bhh1[tid];
    }

    // my half-row of Wih1/Whh1 in registers, paired over k
    ull w1x[16], w1h[16];
    {
        const float4* px = (const float4*)(Wih1 + r * 64 + hh * 32);
        const float4* ph = (const float4*)(Whh1 + r * 64 + hh * 32);
#pragma unroll
        for (int i = 0; i < 8; i++) {
            float4 vx = __ldg(px + i), vh = __ldg(ph + i);
            w1x[2 * i] = pack2(vx.x, vx.y); w1x[2 * i + 1] = pack2(vx.z, vx.w);
            w1h[2 * i] = pack2(vh.x, vh.y); w1h[2 * i + 1] = pack2(vh.z, vh.w);
        }
    }

    const int b0 = blockIdx.x * NB;
    // cellA threads (tid<256) read xproj for their 4 gate rows
    const float* xbase = g_xproj + (size_t)(b0 + cnb) * SLEN * GDIM + cj;
    float c0 = 0.0f, c1 = 0.0f;   // c0 valid tid<256, c1 valid tid>=256
    float xcur[4];
    if (tid < 256) {
#pragma unroll
        for (int g = 0; g < 4; g++) xcur[g] = __ldg(xbase + g * 64);
    }

    const uint32_t s_w0 = smem_u32(W0s) + r * (KB_WPAD * 4) + hh * 128;
    const uint32_t s_h0 = smem_u32(h0s) + hh * 128;
    const uint32_t s_h1 = smem_u32(h1s) + hh * 128;
    const uint32_t s_psA = smem_u32(psA);
    const uint32_t s_psB = smem_u32(psB);
    __syncthreads();

    for (int t = 0; t < SLEN; t++) {
        // ---- I1: cellB(t-1) [tid>=256] overlapped with phaseA(t) partials ----
        if (tid >= 256 && t > 0) {
            float p0 = psB[cnb * 256 + cj]        + psB[1024 + cnb * 256 + cj]        + b1s[cj];
            float p1 = psB[cnb * 256 + cj + 64]   + psB[1024 + cnb * 256 + cj + 64]   + b1s[cj + 64];
            float p2 = psB[cnb * 256 + cj + 128]  + psB[1024 + cnb * 256 + cj + 128]  + b1s[cj + 128];
            float p3 = psB[cnb * 256 + cj + 192]  + psB[1024 + cnb * 256 + cj + 192]  + b1s[cj + 192];
            float gi = sig_ap(p0), gf = sig_ap(p1), gg = tanh_ap(p2), go = sig_ap(p3);
            c1 = gf * c1 + gi * gg;
            h1s[cnb * 64 + cj] = go * tanh_ap(c1);
        }
        // phaseA partial: Whh0[r][hh-half] . h0[nb][hh-half]
        {
            ull aa[4] = {0, 0, 0, 0}, ab[4] = {0, 0, 0, 0};
#pragma unroll
            for (int k4 = 0; k4 < 8; k4++) {
                ull w01, w23;
                lds_2x64(w01, w23, s_w0 + k4 * 16);
#pragma unroll
                for (int nb = 0; nb < 4; nb++) {
                    ull h01, h23;
                    lds_2x64(h01, h23, s_h0 + nb * 256 + k4 * 16);
                    aa[nb] = fma2(w01, h01, aa[nb]);
                    ab[nb] = fma2(w23, h23, ab[nb]);
                }
            }
#pragma unroll
            for (int nb = 0; nb < 4; nb++)
                psA[hh * 1024 + nb * 256 + r] = hadd2(aa[nb]) + hadd2(ab[nb]);
        }
        __syncthreads();                                  // bar1

        // ---- I2: cellA(t) [tid<256] + x prefetch ----
        if (tid < 256) {
            const int tn = (t + 1 < SLEN) ? t + 1 : t;
            float xn[4];
#pragma unroll
            for (int g = 0; g < 4; g++)
                xn[g] = __ldg(xbase + (size_t)tn * GDIM + g * 64);
            float p0 = psA[cnb * 256 + cj]       + psA[1024 + cnb * 256 + cj]       + xcur[0];
            float p1 = psA[cnb * 256 + cj + 64]  + psA[1024 + cnb * 256 + cj + 64]  + xcur[1];
            float p2 = psA[cnb * 256 + cj + 128] + psA[1024 + cnb * 256 + cj + 128] + xcur[2];
            float p3 = psA[cnb * 256 + cj + 192] + psA[1024 + cnb * 256 + cj + 192] + xcur[3];
            float gi = sig_ap(p0), gf = sig_ap(p1), gg = tanh_ap(p2), go = sig_ap(p3);
            c0 = gf * c0 + gi * gg;
            h0s[cnb * 64 + cj] = go * tanh_ap(c0);
#pragma unroll
            for (int g = 0; g < 4; g++) xcur[g] = xn[g];
        }
        __syncthreads();                                  // bar2

        // ---- I3: phaseB partial: Wih1.h0(t) + Whh1.h1(t-1), halves ----
        {
            ull aa[4] = {0, 0, 0, 0}, ab[4] = {0, 0, 0, 0};
#pragma unroll
            for (int k4 = 0; k4 < 8; k4++) {
#pragma unroll
                for (int nb = 0; nb < 4; nb++) {
                    ull p01, p23, q01, q23;
                    lds_2x64(p01, p23, s_h0 + nb * 256 + k4 * 16);
                    lds_2x64(q01, q23, s_h1 + nb * 256 + k4 * 16);
                    aa[nb] = fma2(w1x[2 * k4], p01, aa[nb]);
                    ab[nb] = fma2(w1x[2 * k4 + 1], p23, ab[nb]);
                    aa[nb] = fma2(w1h[2 * k4], q01, aa[nb]);
                    ab[nb] = fma2(w1h[2 * k4 + 1], q23, ab[nb]);
                }
            }
#pragma unroll
            for (int nb = 0; nb < 4; nb++)
                psB[hh * 1024 + nb * 256 + r] = hadd2(aa[nb]) + hadd2(ab[nb]);
        }
        __syncthreads();                                  // bar3
    }

    // final cellB(511)
    if (tid >= 256) {
        float p0 = psB[cnb * 256 + cj]       + psB[1024 + cnb * 256 + cj]       + b1s[cj];
        float p1 = psB[cnb * 256 + cj + 64]  + psB[1024 + cnb * 256 + cj + 64]  + b1s[cj + 64];
        float p2 = psB[cnb * 256 + cj + 128] + psB[1024 + cnb * 256 + cj + 128] + b1s[cj + 128];
        float p3 = psB[cnb * 256 + cj + 192] + psB[1024 + cnb * 256 + cj + 192] + b1s[cj + 192];
        float gi = sig_ap(p0), gf = sig_ap(p1), gg = tanh_ap(p2), go = sig_ap(p3);
        c1 = gf * c1 + gi * gg;
        h1s[cnb * 64 + cj] = go * tanh_ap(c1);
    }
    __syncthreads();

    if (tid < 2 * NB) {
        const int nb = tid >> 1, o = tid & 1;
        float s = bfc[o];
#pragma unroll
        for (int k = 0; k < HDIM; k++)
            s += Wfc[o * HDIM + k] * h1s[nb * HDIM + k];
        out[(b0 + nb) * 2 + o] = 1.0f / (1.0f + __expf(-s));
    }
}

// ================================ launcher =====================================
extern "C" void kernel_launch(void* const* d_in, const int* in_sizes, int n_in,
                              void* d_out, int out_size) {
    const int*   seq  = (const int*)d_in[0];
    const float* emb  = (const float*)d_in[1];
    const float* Wih0 = (const float*)d_in[2];
    const float* Whh0 = (const float*)d_in[3];
    const float* bih0 = (const float*)d_in[4];
    const float* bhh0 = (const float*)d_in[5];
    const float* Wih1 = (const float*)d_in[6];
    const float* Whh1 = (const float*)d_in[7];
    const float* bih1 = (const float*)d_in[8];
    const float* bhh1 = (const float*)d_in[9];
    const float* Wfc  = (const float*)d_in[10];
    const float* bfc  = (const float*)d_in[11];
    float* out = (float*)d_out;

    cudaFuncSetAttribute(embed_xproj_kernel,
                         cudaFuncAttributeMaxDynamicSharedMemorySize, KA_SMEM);
    cudaFuncSetAttribute(lstm_rec_kernel,
                         cudaFuncAttributeMaxDynamicSharedMemorySize, KB_SMEM);

    embed_xproj_kernel<<<148, 256, KA_SMEM>>>(seq, emb, Wih0, bih0, bhh0);
    lstm_rec_kernel<<<BSZ / NB, 512, KB_SMEM>>>(Whh0, Wih1, Whh1, bih1, bhh1,
                                                Wfc, bfc, out);
}

// round 8
// speedup vs baseline: 1.3912x; 1.3912x over previous
#include <cuda_runtime.h>
#include <cstdint>

#define EV 50000
#define EDIM 128
#define HDIM 64
#define GDIM 256
#define BSZ 512
#define SLEN 512
#define NB 4
typedef unsigned long long ull;

__device__ float g_xproj[(size_t)BSZ * SLEN * GDIM];

__device__ __forceinline__ uint32_t smem_u32(const void* p) {
    uint32_t a;
    asm("{ .reg .u64 t; cvta.to.shared.u64 t, %1; cvt.u32.u64 %0, t; }"
        : "=r"(a) : "l"(p));
    return a;
}
__device__ __forceinline__ ull fma2(ull a, ull b, ull c) {
    ull d; asm("fma.rn.f32x2 %0, %1, %2, %3;" : "=l"(d) : "l"(a), "l"(b), "l"(c));
    return d;
}
__device__ __forceinline__ void lds_2x64(ull& a, ull& b, uint32_t addr) {
    asm volatile("ld.shared.v2.u64 {%0, %1}, [%2];" : "=l"(a), "=l"(b) : "r"(addr));
}
__device__ __forceinline__ float hadd2(ull v) {
    float lo, hi; asm("mov.b64 {%0, %1}, %2;" : "=f"(lo), "=f"(hi) : "l"(v));
    return lo + hi;
}
__device__ __forceinline__ ull pack2(float lo, float hi) {
    ull d; asm("mov.b64 %0, {%1, %2};" : "=l"(d) : "f"(lo), "f"(hi));
    return d;
}
__device__ __forceinline__ float tanh_ap(float x) {
    float y; asm("tanh.approx.f32 %0, %1;" : "=f"(y) : "f"(x));
    return y;
}
__device__ __forceinline__ float gate_act(float x, bool is_tanh) {
    float y = tanh_ap(is_tanh ? x : 0.5f * x);
    return is_tanh ? y : 0.5f * y + 0.5f;
}
__device__ __forceinline__ uint32_t to_tf32(float f) {
    uint32_t r;
    asm("cvt.rna.tf32.f32 %0, %1;" : "=r"(r) : "f"(f));
    return r;
}
// D += A*B : m16n8k8 tf32
__device__ __forceinline__ void mma_tf32(float* d, const uint32_t* a,
                                         const uint32_t* b) {
    asm volatile(
        "mma.sync.aligned.m16n8k8.row.col.f32.tf32.tf32.f32 "
        "{%0,%1,%2,%3}, {%4,%5,%6,%7}, {%8,%9}, {%0,%1,%2,%3};"
        : "+f"(d[0]), "+f"(d[1]), "+f"(d[2]), "+f"(d[3])
        : "r"(a[0]), "r"(a[1]), "r"(a[2]), "r"(a[3]), "r"(b[0]), "r"(b[1]));
}

// ============ Kernel A: embed + x@Wih0^T + bias via tf32 mma.sync ==============
// Tile: 64 tokens x 256 gates, K=128. 8 warps: warp w owns gates [32w, 32w+32).
// smem: Ws [256][132] tf32, xs [64][132] tf32, bias [256].
#define KM_PAD 132
#define KM_SMEM ((256 * KM_PAD + 64 * KM_PAD + 256) * 4)

__global__ void __launch_bounds__(256, 1)
embed_xproj_mma(const int* __restrict__ seq, const float* __restrict__ emb,
                const float* __restrict__ Wih0, const float* __restrict__ bih0,
                const float* __restrict__ bhh0) {
    extern __shared__ float sm[];
    float* Ws = sm;                    // [256][132] (tf32 bit patterns)
    float* xs = Ws + 256 * KM_PAD;     // [64][132]
    float* bs = xs + 64 * KM_PAD;      // [256]
    const uint32_t* Wsu = (const uint32_t*)Ws;
    const uint32_t* xsu = (const uint32_t*)xs;

    const int tid = threadIdx.x;
    const int lane = tid & 31, w = tid >> 5;
    const int gid = lane >> 2, tig = lane & 3;
    const int n_base = w * 32;

    // stage weights, cvt to tf32
    for (int i = tid; i < 256 * 32; i += 256) {
        int g = i >> 5, k4 = i & 31;
        float4 v = ((const float4*)Wih0)[(size_t)g * 32 + k4];
        uint4 u;
        u.x = to_tf32(v.x); u.y = to_tf32(v.y);
        u.z = to_tf32(v.z); u.w = to_tf32(v.w);
        *(uint4*)&Ws[g * KM_PAD + k4 * 4] = u;
    }
    if (tid < 256) bs[tid] = bih0[tid] + bhh0[tid];

    // gather: thread -> token tid>>2, k-quarter (tid&3)*32 (8 float4)
    const int mytok = tid >> 2, kq = tid & 3;
    const int ntiles = (BSZ * SLEN) / 64;   // 4096
    float4 pf[8];

    auto ldx = [&](int tile) {
        int idx = __ldg(seq + tile * 64 + mytok);
        idx = idx < 0 ? 0 : (idx >= EV ? EV - 1 : idx);
        const float4* er = (const float4*)emb + (size_t)idx * 32 + kq * 8;
#pragma unroll
        for (int i = 0; i < 8; i++) pf[i] = __ldg(er + i);
    };
    auto stx = [&]() {
#pragma unroll
        for (int i = 0; i < 8; i++) {
            uint4 u;
            u.x = to_tf32(pf[i].x); u.y = to_tf32(pf[i].y);
            u.z = to_tf32(pf[i].z); u.w = to_tf32(pf[i].w);
            *(uint4*)&xs[mytok * KM_PAD + kq * 32 + i * 4] = u;
        }
    };

    int tile = blockIdx.x;
    if (tile < ntiles) ldx(tile);
    __syncthreads();
    if (tile < ntiles) stx();
    __syncthreads();

    for (; tile < ntiles; tile += gridDim.x) {
        const int nxt = tile + gridDim.x;
        if (nxt < ntiles) ldx(nxt);

        float acc[4][4][4];   // [m-block][n-block][frag]
#pragma unroll
        for (int mb = 0; mb < 4; mb++)
#pragma unroll
            for (int nb = 0; nb < 4; nb++)
#pragma unroll
                for (int i = 0; i < 4; i++) acc[mb][nb][i] = 0.0f;

#pragma unroll 4
        for (int kk = 0; kk < 16; kk++) {
            uint32_t a[4][4], b[4][2];
#pragma unroll
            for (int mb = 0; mb < 4; mb++) {
                int base = (mb * 16 + gid) * KM_PAD + kk * 8 + tig;
                a[mb][0] = xsu[base];
                a[mb][1] = xsu[base + 8 * KM_PAD];
                a[mb][2] = xsu[base + 4];
                a[mb][3] = xsu[base + 8 * KM_PAD + 4];
            }
#pragma unroll
            for (int nb = 0; nb < 4; nb++) {
                int base = (n_base + nb * 8 + gid) * KM_PAD + kk * 8 + tig;
                b[nb][0] = Wsu[base];
                b[nb][1] = Wsu[base + 4];
            }
#pragma unroll
            for (int mb = 0; mb < 4; mb++)
#pragma unroll
                for (int nb = 0; nb < 4; nb++)
                    mma_tf32(acc[mb][nb], a[mb], b[nb]);
        }

        // store: D[m16 x n8] frags: d0(gid,2tig) d1(gid,2tig+1) d2(gid+8,..) d3
#pragma unroll
        for (int mb = 0; mb < 4; mb++) {
#pragma unroll
            for (int nb = 0; nb < 4; nb++) {
                const int token = tile * 64 + mb * 16 + gid;
                const int gate = n_base + nb * 8 + 2 * tig;
                float2 bia = *(float2*)&bs[gate];
                float2 v0 = {acc[mb][nb][0] + bia.x, acc[mb][nb][1] + bia.y};
                float2 v1 = {acc[mb][nb][2] + bia.x, acc[mb][nb][3] + bia.y};
                *(float2*)&g_xproj[(size_t)token * GDIM + gate] = v0;
                *(float2*)&g_xproj[(size_t)(token + 8) * GDIM + gate] = v1;
            }
        }
        __syncthreads();
        if (nxt < ntiles) stx();
        __syncthreads();
    }
}

// ============ Kernel B: R4 exact (best: 1085 us) ===============================
#define KB_WPAD 68
#define KB_SMEM ((GDIM * KB_WPAD + 2 * NB * HDIM + NB * GDIM) * 4)

__global__ void __launch_bounds__(256, 1)
lstm_rec_kernel(const float* __restrict__ Whh0, const float* __restrict__ Wih1,
                const float* __restrict__ Whh1, const float* __restrict__ bih1,
                const float* __restrict__ bhh1, const float* __restrict__ Wfc,
                const float* __restrict__ bfc, float* __restrict__ out) {
    extern __shared__ float sm[];
    float* W0s = sm;                      // Whh0 [256][68]
    float* h0s = W0s + GDIM * KB_WPAD;    // [4][64]
    float* h1s = h0s + NB * HDIM;         // [4][64]
    float* gs  = h1s + NB * HDIM;         // [4][256]
    const int tid = threadIdx.x;

    for (int i = tid; i < GDIM * 16; i += 256) {
        int g = i >> 4, k4 = i & 15;
        *(float4*)&W0s[g * KB_WPAD + k4 * 4] = ((const float4*)Whh0)[i];
    }
    h0s[tid] = 0.0f;
    h1s[tid] = 0.0f;

    ull w1x[32], w1h[32];
    {
        const float4* px = (const float4*)(Wih1 + tid * 64);
        const float4* ph = (const float4*)(Whh1 + tid * 64);
#pragma unroll
        for (int i = 0; i < 16; i++) {
            float4 vx = __ldg(px + i), vh = __ldg(ph + i);
            w1x[2 * i] = pack2(vx.x, vx.y); w1x[2 * i + 1] = pack2(vx.z, vx.w);
            w1h[2 * i] = pack2(vh.x, vh.y); w1h[2 * i + 1] = pack2(vh.z, vh.w);
        }
    }
    const float b1 = bih1[tid] + bhh1[tid];
    const bool my_tanh = (tid >= 128 && tid < 192);
    float c0[NB] = {0.f, 0.f, 0.f, 0.f};
    float c1[NB] = {0.f, 0.f, 0.f, 0.f};
    __syncthreads();

    const int b0 = blockIdx.x * NB;
    const float* xrow[NB];
#pragma unroll
    for (int nb = 0; nb < NB; nb++)
        xrow[nb] = g_xproj + (size_t)(b0 + nb) * SLEN * GDIM + tid;

    const uint32_t s_w0 = smem_u32(W0s) + tid * (KB_WPAD * 4);
    const uint32_t s_h0 = smem_u32(h0s);
    const uint32_t s_h1 = smem_u32(h1s);

    float xcur[NB];
#pragma unroll
    for (int nb = 0; nb < NB; nb++) xcur[nb] = __ldg(xrow[nb]);

    for (int t = 0; t < SLEN; t++) {
        float xnxt[NB];
        const int tn = (t + 1 < SLEN) ? t + 1 : t;
#pragma unroll
        for (int nb = 0; nb < NB; nb++)
            xnxt[nb] = __ldg(xrow[nb] + (size_t)tn * GDIM);

        ull aa[NB], ab[NB];
#pragma unroll
        for (int nb = 0; nb < NB; nb++) { aa[nb] = 0; ab[nb] = 0; }
#pragma unroll
        for (int k4 = 0; k4 < 16; k4++) {
            ull w01, w23;
            lds_2x64(w01, w23, s_w0 + k4 * 16);
#pragma unroll
            for (int nb = 0; nb < NB; nb++) {
                ull h01, h23;
                lds_2x64(h01, h23, s_h0 + (nb * HDIM + k4 * 4) * 4);
                aa[nb] = fma2(w01, h01, aa[nb]);
                ab[nb] = fma2(w23, h23, ab[nb]);
            }
        }
#pragma unroll
        for (int nb = 0; nb < NB; nb++)
            gs[nb * GDIM + tid] =
                gate_act(hadd2(aa[nb]) + hadd2(ab[nb]) + xcur[nb], my_tanh);
        __syncthreads();

        if (tid < HDIM) {
#pragma unroll
            for (int nb = 0; nb < NB; nb++) {
                const float* gb = gs + nb * GDIM;
                float gi = gb[tid], gf = gb[64 + tid];
                float gg = gb[128 + tid], go = gb[192 + tid];
                c0[nb] = gf * c0[nb] + gi * gg;
                h0s[nb * HDIM + tid] = go * tanh_ap(c0[nb]);
            }
        }
        __syncthreads();

#pragma unroll
        for (int nb = 0; nb < NB; nb++) { aa[nb] = 0; ab[nb] = 0; }
#pragma unroll
        for (int k4 = 0; k4 < 16; k4++) {
#pragma unroll
            for (int nb = 0; nb < NB; nb++) {
                ull p01, p23, q01, q23;
                lds_2x64(p01, p23, s_h0 + (nb * HDIM + k4 * 4) * 4);
                lds_2x64(q01, q23, s_h1 + (nb * HDIM + k4 * 4) * 4);
                aa[nb] = fma2(w1x[2 * k4], p01, aa[nb]);
                ab[nb] = fma2(w1x[2 * k4 + 1], p23, ab[nb]);
                aa[nb] = fma2(w1h[2 * k4], q01, aa[nb]);
                ab[nb] = fma2(w1h[2 * k4 + 1], q23, ab[nb]);
            }
        }
#pragma unroll
        for (int nb = 0; nb < NB; nb++)
            gs[nb * GDIM + tid] =
                gate_act(hadd2(aa[nb]) + hadd2(ab[nb]) + b1, my_tanh);
        __syncthreads();

        if (tid < HDIM) {
#pragma unroll
            for (int nb = 0; nb < NB; nb++) {
                const float* gb = gs + nb * GDIM;
                float gi = gb[tid], gf = gb[64 + tid];
                float gg = gb[128 + tid], go = gb[192 + tid];
                c1[nb] = gf * c1[nb] + gi * gg;
                h1s[nb * HDIM + tid] = go * tanh_ap(c1[nb]);
            }
        }
        __syncthreads();

#pragma unroll
        for (int nb = 0; nb < NB; nb++) xcur[nb] = xnxt[nb];
    }

    if (tid < 2 * NB) {
        const int nb = tid >> 1, o = tid & 1;
        float s = bfc[o];
#pragma unroll
        for (int k = 0; k < HDIM; k++)
            s += Wfc[o * HDIM + k] * h1s[nb * HDIM + k];
        out[(b0 + nb) * 2 + o] = 1.0f / (1.0f + __expf(-s));
    }
}

// ================================ launcher =====================================
extern "C" void kernel_launch(void* const* d_in, const int* in_sizes, int n_in,
                              void* d_out, int out_size) {
    const int*   seq  = (const int*)d_in[0];
    const float* emb  = (const float*)d_in[1];
    const float* Wih0 = (const float*)d_in[2];
    const float* Whh0 = (const float*)d_in[3];
    const float* bih0 = (const float*)d_in[4];
    const float* bhh0 = (const float*)d_in[5];
    const float* Wih1 = (const float*)d_in[6];
    const float* Whh1 = (const float*)d_in[7];
    const float* bih1 = (const float*)d_in[8];
    const float* bhh1 = (const float*)d_in[9];
    const float* Wfc  = (const float*)d_in[10];
    const float* bfc  = (const float*)d_in[11];
    float* out = (float*)d_out;

    cudaFuncSetAttribute(embed_xproj_mma,
                         cudaFuncAttributeMaxDynamicSharedMemorySize, KM_SMEM);
    cudaFuncSetAttribute(lstm_rec_kernel,
                         cudaFuncAttributeMaxDynamicSharedMemorySize, KB_SMEM);

    embed_xproj_mma<<<148, 256, KM_SMEM>>>(seq, emb, Wih0, bih0, bhh0);
    lstm_rec_kernel<<<BSZ / NB, 256, KB_SMEM>>>(Whh0, Wih1, Whh1, bih1, bhh1,
                                                Wfc, bfc, out);
}

// round 9
// speedup vs baseline: 2.9657x; 2.1317x over previous
#include <cuda_runtime.h>
#include <cuda_fp16.h>
#include <cstdint>

#define EV 50000
#define EDIM 128
#define HDIM 64
#define GDIM 256
#define BSZ 512
#define SLEN 512
#define NB 4
typedef unsigned long long ull;

__device__ float g_xproj[(size_t)BSZ * SLEN * GDIM];

__device__ __forceinline__ uint32_t smem_u32(const void* p) {
    uint32_t a;
    asm("{ .reg .u64 t; cvta.to.shared.u64 t, %1; cvt.u32.u64 %0, t; }"
        : "=r"(a) : "l"(p));
    return a;
}
__device__ __forceinline__ float tanh_ap(float x) {
    float y; asm("tanh.approx.f32 %0, %1;" : "=f"(y) : "f"(x));
    return y;
}
__device__ __forceinline__ float sig_ap(float x) {
    return 0.5f * tanh_ap(0.5f * x) + 0.5f;
}
__device__ __forceinline__ uint32_t to_tf32(float f) {
    uint32_t r;
    asm("cvt.rna.tf32.f32 %0, %1;" : "=r"(r) : "f"(f));
    return r;
}
__device__ __forceinline__ void mma_tf32(float* d, const uint32_t* a,
                                         const uint32_t* b) {
    asm volatile(
        "mma.sync.aligned.m16n8k8.row.col.f32.tf32.tf32.f32 "
        "{%0,%1,%2,%3}, {%4,%5,%6,%7}, {%8,%9}, {%0,%1,%2,%3};"
        : "+f"(d[0]), "+f"(d[1]), "+f"(d[2]), "+f"(d[3])
        : "r"(a[0]), "r"(a[1]), "r"(a[2]), "r"(a[3]), "r"(b[0]), "r"(b[1]));
}
__device__ __forceinline__ void mma_f16(float* d, const uint32_t* a,
                                        const uint32_t* b) {
    asm volatile(
        "mma.sync.aligned.m16n8k16.row.col.f32.f16.f16.f32 "
        "{%0,%1,%2,%3}, {%4,%5,%6,%7}, {%8,%9}, {%0,%1,%2,%3};"
        : "+f"(d[0]), "+f"(d[1]), "+f"(d[2]), "+f"(d[3])
        : "r"(a[0]), "r"(a[1]), "r"(a[2]), "r"(a[3]), "r"(b[0]), "r"(b[1]));
}
__device__ __forceinline__ void ldsm_x4(uint32_t* r, uint32_t addr) {
    asm volatile(
        "ldmatrix.sync.aligned.m8n8.x4.shared.b16 {%0,%1,%2,%3}, [%4];"
        : "=r"(r[0]), "=r"(r[1]), "=r"(r[2]), "=r"(r[3]) : "r"(addr));
}
__device__ __forceinline__ uint32_t packh2(float lo, float hi) {
    __half2 h = __floats2half2_rn(lo, hi);
    return *(uint32_t*)&h;
}

// ============ Kernel A: embed + x@Wih0^T + bias via tf32 mma (R8 exact) ========
#define KM_PAD 132
#define KM_SMEM ((256 * KM_PAD + 64 * KM_PAD + 256) * 4)

__global__ void __launch_bounds__(256, 1)
embed_xproj_mma(const int* __restrict__ seq, const float* __restrict__ emb,
                const float* __restrict__ Wih0, const float* __restrict__ bih0,
                const float* __restrict__ bhh0) {
    extern __shared__ float sm[];
    float* Ws = sm;
    float* xs = Ws + 256 * KM_PAD;
    float* bs = xs + 64 * KM_PAD;
    const uint32_t* Wsu = (const uint32_t*)Ws;
    const uint32_t* xsu = (const uint32_t*)xs;

    const int tid = threadIdx.x;
    const int lane = tid & 31, w = tid >> 5;
    const int gid = lane >> 2, tig = lane & 3;
    const int n_base = w * 32;

    for (int i = tid; i < 256 * 32; i += 256) {
        int g = i >> 5, k4 = i & 31;
        float4 v = ((const float4*)Wih0)[(size_t)g * 32 + k4];
        uint4 u;
        u.x = to_tf32(v.x); u.y = to_tf32(v.y);
        u.z = to_tf32(v.z); u.w = to_tf32(v.w);
        *(uint4*)&Ws[g * KM_PAD + k4 * 4] = u;
    }
    if (tid < 256) bs[tid] = bih0[tid] + bhh0[tid];

    const int mytok = tid >> 2, kq = tid & 3;
    const int ntiles = (BSZ * SLEN) / 64;
    float4 pf[8];

    auto ldx = [&](int tile) {
        int idx = __ldg(seq + tile * 64 + mytok);
        idx = idx < 0 ? 0 : (idx >= EV ? EV - 1 : idx);
        const float4* er = (const float4*)emb + (size_t)idx * 32 + kq * 8;
#pragma unroll
        for (int i = 0; i < 8; i++) pf[i] = __ldg(er + i);
    };
    auto stx = [&]() {
#pragma unroll
        for (int i = 0; i < 8; i++) {
            uint4 u;
            u.x = to_tf32(pf[i].x); u.y = to_tf32(pf[i].y);
            u.z = to_tf32(pf[i].z); u.w = to_tf32(pf[i].w);
            *(uint4*)&xs[mytok * KM_PAD + kq * 32 + i * 4] = u;
        }
    };

    int tile = blockIdx.x;
    if (tile < ntiles) ldx(tile);
    __syncthreads();
    if (tile < ntiles) stx();
    __syncthreads();

    for (; tile < ntiles; tile += gridDim.x) {
        const int nxt = tile + gridDim.x;
        if (nxt < ntiles) ldx(nxt);

        float acc[4][4][4];
#pragma unroll
        for (int mb = 0; mb < 4; mb++)
#pragma unroll
            for (int nb = 0; nb < 4; nb++)
#pragma unroll
                for (int i = 0; i < 4; i++) acc[mb][nb][i] = 0.0f;

#pragma unroll 4
        for (int kk = 0; kk < 16; kk++) {
            uint32_t a[4][4], b[4][2];
#pragma unroll
            for (int mb = 0; mb < 4; mb++) {
                int base = (mb * 16 + gid) * KM_PAD + kk * 8 + tig;
                a[mb][0] = xsu[base];
                a[mb][1] = xsu[base + 8 * KM_PAD];
                a[mb][2] = xsu[base + 4];
                a[mb][3] = xsu[base + 8 * KM_PAD + 4];
            }
#pragma unroll
            for (int nb = 0; nb < 4; nb++) {
                int base = (n_base + nb * 8 + gid) * KM_PAD + kk * 8 + tig;
                b[nb][0] = Wsu[base];
                b[nb][1] = Wsu[base + 4];
            }
#pragma unroll
            for (int mb = 0; mb < 4; mb++)
#pragma unroll
                for (int nb = 0; nb < 4; nb++)
                    mma_tf32(acc[mb][nb], a[mb], b[nb]);
        }

#pragma unroll
        for (int mb = 0; mb < 4; mb++) {
#pragma unroll
            for (int nb = 0; nb < 4; nb++) {
                const int token = tile * 64 + mb * 16 + gid;
                const int gate = n_base + nb * 8 + 2 * tig;
                float2 bia = *(float2*)&bs[gate];
                float2 v0 = {acc[mb][nb][0] + bia.x, acc[mb][nb][1] + bia.y};
                float2 v1 = {acc[mb][nb][2] + bia.x, acc[mb][nb][3] + bia.y};
                *(float2*)&g_xproj[(size_t)token * GDIM + gate] = v0;
                *(float2*)&g_xproj[(size_t)(token + 8) * GDIM + gate] = v1;
            }
        }
        __syncthreads();
        if (nxt < ntiles) stx();
        __syncthreads();
    }
}

// ============ Kernel B: recurrence on tensor cores (fp16 in, fp32 acc) =========
// 128 CTAs x 256 thr. Warp w owns gates [32w,32w+32) for BOTH layers.
// h0/h1 in smem fp16 [16][72] (rows 0-3 real, 4-15 zero; 144B row stride ->
// conflict-free ldmatrix). Weights in register fragments. 3 barriers/step.
#define HROWB 144
#define KBM_SMEM (2 * 16 * HROWB + 2 * 1024 * 4 + 256 * 4)   // 13824 B

__global__ void __launch_bounds__(256, 1)
lstm_rec_mma(const float* __restrict__ Whh0, const float* __restrict__ Wih1,
             const float* __restrict__ Whh1, const float* __restrict__ bih1,
             const float* __restrict__ bhh1, const float* __restrict__ Wfc,
             const float* __restrict__ bfc, float* __restrict__ out) {
    extern __shared__ char smc[];
    __half* h0h = (__half*)smc;                    // [16][72]
    __half* h1h = (__half*)(smc + 16 * HROWB);     // [16][72]
    float* psA = (float*)(smc + 32 * HROWB);       // [4][256]
    float* psB = psA + 1024;                       // [4][256]
    float* h1f = psB + 1024;                       // [4][64]

    const int tid = threadIdx.x;
    const int lane = tid & 31, w = tid >> 5;
    const int gid = lane >> 2, tig = lane & 3;
    const int nbase = w * 32;
    const int cnb = tid >> 6, cj = tid & 63;       // my cell (batch, hidden)

    // zero both h buffers (4608 B = 1152 u32)
    for (int i = tid; i < 1152; i += 256) ((uint32_t*)smc)[i] = 0;

    // weight fragments: B-frag b0={W[g][2tig],W[g][2tig+1]}, b1={.. +8,+9}
    uint32_t fw0[4][4][2], fw1[4][8][2];
#pragma unroll
    for (int nb2 = 0; nb2 < 4; nb2++) {
        const int g = nbase + nb2 * 8 + gid;
        const float* r0 = Whh0 + g * 64;
        const float* rx = Wih1 + g * 64;
        const float* rh = Whh1 + g * 64;
#pragma unroll
        for (int kt = 0; kt < 4; kt++) {
            const int k0 = kt * 16 + 2 * tig;
            fw0[nb2][kt][0] = packh2(__ldg(r0 + k0), __ldg(r0 + k0 + 1));
            fw0[nb2][kt][1] = packh2(__ldg(r0 + k0 + 8), __ldg(r0 + k0 + 9));
            fw1[nb2][kt][0] = packh2(__ldg(rx + k0), __ldg(rx + k0 + 1));
            fw1[nb2][kt][1] = packh2(__ldg(rx + k0 + 8), __ldg(rx + k0 + 9));
            fw1[nb2][kt + 4][0] = packh2(__ldg(rh + k0), __ldg(rh + k0 + 1));
            fw1[nb2][kt + 4][1] = packh2(__ldg(rh + k0 + 8), __ldg(rh + k0 + 9));
        }
    }
    // bias for my cell's 4 gates
    const float bb0 = __ldg(bih1 + cj) + __ldg(bhh1 + cj);
    const float bb1 = __ldg(bih1 + 64 + cj) + __ldg(bhh1 + 64 + cj);
    const float bb2 = __ldg(bih1 + 128 + cj) + __ldg(bhh1 + 128 + cj);
    const float bb3 = __ldg(bih1 + 192 + cj) + __ldg(bhh1 + 192 + cj);

    // ldmatrix per-lane address offset
    const int mi = lane >> 3, rr = lane & 7;
    const uint32_t aoff = (uint32_t)(((mi & 1) * 8 + rr) * HROWB + ((mi >> 1) * 8) * 2);
    const uint32_t a0b = smem_u32(h0h) + aoff;
    const uint32_t a1b = smem_u32(h1h) + aoff;

    const int b0i = blockIdx.x * NB;
    const float* xb = g_xproj + (size_t)(b0i + cnb) * SLEN * GDIM + cj;
    float c0 = 0.0f, c1 = 0.0f;
    float xq0 = __ldg(xb), xq1 = __ldg(xb + 64), xq2 = __ldg(xb + 128),
          xq3 = __ldg(xb + 192);
    __syncthreads();

    for (int t = 0; t < SLEN; t++) {
        // ---- I1: cellB(t-1) overlapped with phaseA(t) ----
        if (t > 0) {
            float pi = psB[cnb * 256 + cj] + bb0;
            float pf = psB[cnb * 256 + 64 + cj] + bb1;
            float pg = psB[cnb * 256 + 128 + cj] + bb2;
            float po = psB[cnb * 256 + 192 + cj] + bb3;
            c1 = sig_ap(pf) * c1 + sig_ap(pi) * tanh_ap(pg);
            h1h[cnb * 72 + cj] = __float2half(sig_ap(po) * tanh_ap(c1));
        }
        // prefetch next x
        const size_t tn = (size_t)((t + 1 < SLEN) ? t + 1 : t) * GDIM;
        float xn0 = __ldg(xb + tn), xn1 = __ldg(xb + tn + 64),
              xn2 = __ldg(xb + tn + 128), xn3 = __ldg(xb + tn + 192);

        // phaseA: preacts0 = h0 @ Whh0^T (my 32-gate slice)
        {
            float acc[4][4] = {{0, 0, 0, 0}, {0, 0, 0, 0}, {0, 0, 0, 0}, {0, 0, 0, 0}};
#pragma unroll
            for (int kt = 0; kt < 4; kt++) {
                uint32_t a[4];
                ldsm_x4(a, a0b + kt * 32);
#pragma unroll
                for (int nb2 = 0; nb2 < 4; nb2++)
                    mma_f16(acc[nb2], a, fw0[nb2][kt]);
            }
            if (gid < 4) {
#pragma unroll
                for (int nb2 = 0; nb2 < 4; nb2++) {
                    float2 v = {acc[nb2][0], acc[nb2][1]};
                    *(float2*)&psA[gid * 256 + nbase + nb2 * 8 + 2 * tig] = v;
                }
            }
        }
        __syncthreads();                                  // bar1

        // ---- I2: cellA(t) ----
        {
            float pi = psA[cnb * 256 + cj] + xq0;
            float pf = psA[cnb * 256 + 64 + cj] + xq1;
            float pg = psA[cnb * 256 + 128 + cj] + xq2;
            float po = psA[cnb * 256 + 192 + cj] + xq3;
            c0 = sig_ap(pf) * c0 + sig_ap(pi) * tanh_ap(pg);
            h0h[cnb * 72 + cj] = __float2half(sig_ap(po) * tanh_ap(c0));
            xq0 = xn0; xq1 = xn1; xq2 = xn2; xq3 = xn3;
        }
        __syncthreads();                                  // bar2

        // ---- I3: phaseB: preacts1 = [h0 h1] @ [Wih1 Whh1]^T ----
        {
            float acc[4][4] = {{0, 0, 0, 0}, {0, 0, 0, 0}, {0, 0, 0, 0}, {0, 0, 0, 0}};
#pragma unroll
            for (int kt = 0; kt < 4; kt++) {
                uint32_t a[4];
                ldsm_x4(a, a0b + kt * 32);
#pragma unroll
                for (int nb2 = 0; nb2 < 4; nb2++)
                    mma_f16(acc[nb2], a, fw1[nb2][kt]);
            }
#pragma unroll
            for (int kt = 0; kt < 4; kt++) {
                uint32_t a[4];
                ldsm_x4(a, a1b + kt * 32);
#pragma unroll
                for (int nb2 = 0; nb2 < 4; nb2++)
                    mma_f16(acc[nb2], a, fw1[nb2][kt + 4]);
            }
            if (gid < 4) {
#pragma unroll
                for (int nb2 = 0; nb2 < 4; nb2++) {
                    float2 v = {acc[nb2][0], acc[nb2][1]};
                    *(float2*)&psB[gid * 256 + nbase + nb2 * 8 + 2 * tig] = v;
                }
            }
        }
        __syncthreads();                                  // bar3
    }

    // final cellB(511) -> h1f (f32)
    {
        float pi = psB[cnb * 256 + cj] + bb0;
        float pf = psB[cnb * 256 + 64 + cj] + bb1;
        float pg = psB[cnb * 256 + 128 + cj] + bb2;
        float po = psB[cnb * 256 + 192 + cj] + bb3;
        c1 = sig_ap(pf) * c1 + sig_ap(pi) * tanh_ap(pg);
        h1f[cnb * 64 + cj] = sig_ap(po) * tanh_ap(c1);
    }
    __syncthreads();

    if (tid < 2 * NB) {
        const int nb = tid >> 1, o = tid & 1;
        float s = bfc[o];
#pragma unroll
        for (int k = 0; k < HDIM; k++)
            s += Wfc[o * HDIM + k] * h1f[nb * HDIM + k];
        out[(b0i + nb) * 2 + o] = 1.0f / (1.0f + __expf(-s));
    }
}

// ================================ launcher =====================================
extern "C" void kernel_launch(void* const* d_in, const int* in_sizes, int n_in,
                              void* d_out, int out_size) {
    const int*   seq  = (const int*)d_in[0];
    const float* emb  = (const float*)d_in[1];
    const float* Wih0 = (const float*)d_in[2];
    const float* Whh0 = (const float*)d_in[3];
    const float* bih0 = (const float*)d_in[4];
    const float* bhh0 = (const float*)d_in[5];
    const float* Wih1 = (const float*)d_in[6];
    const float* Whh1 = (const float*)d_in[7];
    const float* bih1 = (const float*)d_in[8];
    const float* bhh1 = (const float*)d_in[9];
    const float* Wfc  = (const float*)d_in[10];
    const float* bfc  = (const float*)d_in[11];
    float* out = (float*)d_out;

    cudaFuncSetAttribute(embed_xproj_mma,
                         cudaFuncAttributeMaxDynamicSharedMemorySize, KM_SMEM);
    cudaFuncSetAttribute(lstm_rec_mma,
                         cudaFuncAttributeMaxDynamicSharedMemorySize, KBM_SMEM);

    embed_xproj_mma<<<148, 256, KM_SMEM>>>(seq, emb, Wih0, bih0, bhh0);
    lstm_rec_mma<<<BSZ / NB, 256, KBM_SMEM>>>(Whh0, Wih1, Whh1, bih1, bhh1,
                                              Wfc, bfc, out);
}

// round 10
// speedup vs baseline: 3.1264x; 1.0542x over previous
#include <cuda_runtime.h>
#include <cuda_fp16.h>
#include <cstdint>

#define EV 50000
#define EDIM 128
#define HDIM 64
#define GDIM 256
#define BSZ 512
#define SLEN 512
#define NB 4
typedef unsigned long long ull;

__device__ float g_xproj[(size_t)BSZ * SLEN * GDIM];

__device__ __forceinline__ uint32_t smem_u32(const void* p) {
    uint32_t a;
    asm("{ .reg .u64 t; cvta.to.shared.u64 t, %1; cvt.u32.u64 %0, t; }"
        : "=r"(a) : "l"(p));
    return a;
}
__device__ __forceinline__ float tanh_ap(float x) {
    float y; asm("tanh.approx.f32 %0, %1;" : "=f"(y) : "f"(x));
    return y;
}
__device__ __forceinline__ float sig_ap(float x) {
    return 0.5f * tanh_ap(0.5f * x) + 0.5f;
}
__device__ __forceinline__ uint32_t to_tf32(float f) {
    uint32_t r;
    asm("cvt.rna.tf32.f32 %0, %1;" : "=r"(r) : "f"(f));
    return r;
}
__device__ __forceinline__ void mma_tf32(float* d, const uint32_t* a,
                                         const uint32_t* b) {
    asm volatile(
        "mma.sync.aligned.m16n8k8.row.col.f32.tf32.tf32.f32 "
        "{%0,%1,%2,%3}, {%4,%5,%6,%7}, {%8,%9}, {%0,%1,%2,%3};"
        : "+f"(d[0]), "+f"(d[1]), "+f"(d[2]), "+f"(d[3])
        : "r"(a[0]), "r"(a[1]), "r"(a[2]), "r"(a[3]), "r"(b[0]), "r"(b[1]));
}
__device__ __forceinline__ void mma_f16(float* d, const uint32_t* a,
                                        const uint32_t* b) {
    asm volatile(
        "mma.sync.aligned.m16n8k16.row.col.f32.f16.f16.f32 "
        "{%0,%1,%2,%3}, {%4,%5,%6,%7}, {%8,%9}, {%0,%1,%2,%3};"
        : "+f"(d[0]), "+f"(d[1]), "+f"(d[2]), "+f"(d[3])
        : "r"(a[0]), "r"(a[1]), "r"(a[2]), "r"(a[3]), "r"(b[0]), "r"(b[1]));
}
__device__ __forceinline__ void ldsm_x4(uint32_t* r, uint32_t addr) {
    asm volatile(
        "ldmatrix.sync.aligned.m8n8.x4.shared.b16 {%0,%1,%2,%3}, [%4];"
        : "=r"(r[0]), "=r"(r[1]), "=r"(r[2]), "=r"(r[3]) : "r"(addr));
}
__device__ __forceinline__ uint32_t packh2(float lo, float hi) {
    __half2 h = __floats2half2_rn(lo, hi);
    return *(uint32_t*)&h;
}

// ============ Kernel A: embed + x@Wih0^T + bias via tf32 mma (R8 exact) ========
#define KM_PAD 132
#define KM_SMEM ((256 * KM_PAD + 64 * KM_PAD + 256) * 4)

__global__ void __launch_bounds__(256, 1)
embed_xproj_mma(const int* __restrict__ seq, const float* __restrict__ emb,
                const float* __restrict__ Wih0, const float* __restrict__ bih0,
                const float* __restrict__ bhh0) {
    extern __shared__ float sm[];
    float* Ws = sm;
    float* xs = Ws + 256 * KM_PAD;
    float* bs = xs + 64 * KM_PAD;
    const uint32_t* Wsu = (const uint32_t*)Ws;
    const uint32_t* xsu = (const uint32_t*)xs;

    const int tid = threadIdx.x;
    const int lane = tid & 31, w = tid >> 5;
    const int gid = lane >> 2, tig = lane & 3;
    const int n_base = w * 32;

    for (int i = tid; i < 256 * 32; i += 256) {
        int g = i >> 5, k4 = i & 31;
        float4 v = ((const float4*)Wih0)[(size_t)g * 32 + k4];
        uint4 u;
        u.x = to_tf32(v.x); u.y = to_tf32(v.y);
        u.z = to_tf32(v.z); u.w = to_tf32(v.w);
        *(uint4*)&Ws[g * KM_PAD + k4 * 4] = u;
    }
    if (tid < 256) bs[tid] = bih0[tid] + bhh0[tid];

    const int mytok = tid >> 2, kq = tid & 3;
    const int ntiles = (BSZ * SLEN) / 64;
    float4 pf[8];

    auto ldx = [&](int tile) {
        int idx = __ldg(seq + tile * 64 + mytok);
        idx = idx < 0 ? 0 : (idx >= EV ? EV - 1 : idx);
        const float4* er = (const float4*)emb + (size_t)idx * 32 + kq * 8;
#pragma unroll
        for (int i = 0; i < 8; i++) pf[i] = __ldg(er + i);
    };
    auto stx = [&]() {
#pragma unroll
        for (int i = 0; i < 8; i++) {
            uint4 u;
            u.x = to_tf32(pf[i].x); u.y = to_tf32(pf[i].y);
            u.z = to_tf32(pf[i].z); u.w = to_tf32(pf[i].w);
            *(uint4*)&xs[mytok * KM_PAD + kq * 32 + i * 4] = u;
        }
    };

    int tile = blockIdx.x;
    if (tile < ntiles) ldx(tile);
    __syncthreads();
    if (tile < ntiles) stx();
    __syncthreads();

    for (; tile < ntiles; tile += gridDim.x) {
        const int nxt = tile + gridDim.x;
        if (nxt < ntiles) ldx(nxt);

        float acc[4][4][4];
#pragma unroll
        for (int mb = 0; mb < 4; mb++)
#pragma unroll
            for (int nb = 0; nb < 4; nb++)
#pragma unroll
                for (int i = 0; i < 4; i++) acc[mb][nb][i] = 0.0f;

#pragma unroll 4
        for (int kk = 0; kk < 16; kk++) {
            uint32_t a[4][4], b[4][2];
#pragma unroll
            for (int mb = 0; mb < 4; mb++) {
                int base = (mb * 16 + gid) * KM_PAD + kk * 8 + tig;
                a[mb][0] = xsu[base];
                a[mb][1] = xsu[base + 8 * KM_PAD];
                a[mb][2] = xsu[base + 4];
                a[mb][3] = xsu[base + 8 * KM_PAD + 4];
            }
#pragma unroll
            for (int nb = 0; nb < 4; nb++) {
                int base = (n_base + nb * 8 + gid) * KM_PAD + kk * 8 + tig;
                b[nb][0] = Wsu[base];
                b[nb][1] = Wsu[base + 4];
            }
#pragma unroll
            for (int mb = 0; mb < 4; mb++)
#pragma unroll
                for (int nb = 0; nb < 4; nb++)
                    mma_tf32(acc[mb][nb], a[mb], b[nb]);
        }

#pragma unroll
        for (int mb = 0; mb < 4; mb++) {
#pragma unroll
            for (int nb = 0; nb < 4; nb++) {
                const int token = tile * 64 + mb * 16 + gid;
                const int gate = n_base + nb * 8 + 2 * tig;
                float2 bia = *(float2*)&bs[gate];
                float2 v0 = {acc[mb][nb][0] + bia.x, acc[mb][nb][1] + bia.y};
                float2 v1 = {acc[mb][nb][2] + bia.x, acc[mb][nb][3] + bia.y};
                *(float2*)&g_xproj[(size_t)token * GDIM + gate] = v0;
                *(float2*)&g_xproj[(size_t)(token + 8) * GDIM + gate] = v1;
            }
        }
        __syncthreads();
        if (nxt < ntiles) stx();
        __syncthreads();
    }
}

// ============ Kernel B: tensor-core recurrence, in-register cell updates =======
// Warp w owns hidden slice [8w,8w+8) for ALL 4 gate types (n-block = gate type).
// After MMA, thread (gid<4, tig) holds i,f,g,o for (batch gid, hidden 8w+2tig,+1)
// entirely in registers -> cell update with no smem round-trip. h double-buffered
// fp16 [16][72] rows (144 B). 2 barriers/step.
#define HROWB 144
#define HBUF  (16 * HROWB)                    // 2304 B per h buffer
#define KBM_SMEM (4 * HBUF + 256 * 4)         // 4 h buffers + h1f[4][64]

__global__ void __launch_bounds__(256, 1)
lstm_rec_mma(const float* __restrict__ Whh0, const float* __restrict__ Wih1,
             const float* __restrict__ Whh1, const float* __restrict__ bih1,
             const float* __restrict__ bhh1, const float* __restrict__ Wfc,
             const float* __restrict__ bfc, float* __restrict__ out) {
    extern __shared__ char smc[];
    // [h0_0][h0_1][h1_0][h1_1][h1f]
    float* h1f = (float*)(smc + 4 * HBUF);

    const int tid = threadIdx.x;
    const int lane = tid & 31, w = tid >> 5;
    const int gid = lane >> 2, tig = lane & 3;
    const bool cellth = (gid < 4);
    const int j0 = w * 8 + 2 * tig;           // my 2 hidden units: j0, j0+1

    // zero all 4 h buffers (4*2304 B = 2304 u32)
    for (int i = tid; i < 2304; i += 256) ((uint32_t*)smc)[i] = 0;

    // weight fragments: n-block nb2 = gate type; W row g = nb2*64 + w*8 + gid
    uint32_t fw0[4][4][2], fw1[4][8][2];
#pragma unroll
    for (int nb2 = 0; nb2 < 4; nb2++) {
        const int g = nb2 * 64 + w * 8 + gid;
        const float* r0 = Whh0 + g * 64;
        const float* rx = Wih1 + g * 64;
        const float* rh = Whh1 + g * 64;
#pragma unroll
        for (int kt = 0; kt < 4; kt++) {
            const int k0 = kt * 16 + 2 * tig;
            fw0[nb2][kt][0] = packh2(__ldg(r0 + k0), __ldg(r0 + k0 + 1));
            fw0[nb2][kt][1] = packh2(__ldg(r0 + k0 + 8), __ldg(r0 + k0 + 9));
            fw1[nb2][kt][0] = packh2(__ldg(rx + k0), __ldg(rx + k0 + 1));
            fw1[nb2][kt][1] = packh2(__ldg(rx + k0 + 8), __ldg(rx + k0 + 9));
            fw1[nb2][kt + 4][0] = packh2(__ldg(rh + k0), __ldg(rh + k0 + 1));
            fw1[nb2][kt + 4][1] = packh2(__ldg(rh + k0 + 8), __ldg(rh + k0 + 9));
        }
    }
    // layer-1 biases for my 2 hidden units x 4 gates
    float2 bq[4];
#pragma unroll
    for (int q = 0; q < 4; q++) {
        const int g = q * 64 + j0;
        bq[q].x = __ldg(bih1 + g) + __ldg(bhh1 + g);
        bq[q].y = __ldg(bih1 + g + 1) + __ldg(bhh1 + g + 1);
    }

    // ldmatrix per-lane address offset (validated layout)
    const int mi = lane >> 3, rr = lane & 7;
    const uint32_t aoff =
        (uint32_t)(((mi & 1) * 8 + rr) * HROWB + ((mi >> 1) * 8) * 2);
    const uint32_t h0base = smem_u32(smc) + aoff;
    const uint32_t h1base = smem_u32(smc) + 2 * HBUF + aoff;
    // cell store addresses (row gid, col j0)
    const uint32_t h0st = smem_u32(smc) + gid * HROWB + j0 * 2;
    const uint32_t h1st = smem_u32(smc) + 2 * HBUF + gid * HROWB + j0 * 2;

    const int b0i = blockIdx.x * NB;
    const float* xr = g_xproj +
        (size_t)(b0i + (cellth ? gid : 0)) * SLEN * GDIM;

    float c0a = 0.f, c0b = 0.f, c1a = 0.f, c1b = 0.f;
    float hva = 0.f, hvb = 0.f;               // last h1 values (for epilogue)
    float2 xq[4];
    if (cellth) {
#pragma unroll
        for (int q = 0; q < 4; q++) xq[q] = *(const float2*)(xr + q * 64 + j0);
    }
    uint32_t hp = 0;
    __syncthreads();

    for (int t = 0; t < SLEN; t++) {
        // prefetch x(t+1)
        float2 xn[4];
        if (cellth) {
            const size_t toff = (size_t)((t + 1 < SLEN) ? t + 1 : t) * GDIM;
#pragma unroll
            for (int q = 0; q < 4; q++)
                xn[q] = *(const float2*)(xr + toff + q * 64 + j0);
        }

        // ---- phaseA: preacts0 = h0[hp] @ Whh0^T ; cell in-register ----
        {
            float acc[4][4] = {{0,0,0,0},{0,0,0,0},{0,0,0,0},{0,0,0,0}};
#pragma unroll
            for (int kt = 0; kt < 4; kt++) {
                uint32_t a[4];
                ldsm_x4(a, h0base + hp * HBUF + kt * 32);
#pragma unroll
                for (int nb2 = 0; nb2 < 4; nb2++)
                    mma_f16(acc[nb2], a, fw0[nb2][kt]);
            }
            if (cellth) {
                float i0 = sig_ap(acc[0][0] + xq[0].x),
                      i1 = sig_ap(acc[0][1] + xq[0].y);
                float f0 = sig_ap(acc[1][0] + xq[1].x),
                      f1 = sig_ap(acc[1][1] + xq[1].y);
                float g0 = tanh_ap(acc[2][0] + xq[2].x),
                      g1 = tanh_ap(acc[2][1] + xq[2].y);
                float o0 = sig_ap(acc[3][0] + xq[3].x),
                      o1 = sig_ap(acc[3][1] + xq[3].y);
                c0a = f0 * c0a + i0 * g0;
                c0b = f1 * c0b + i1 * g1;
                uint32_t hv = packh2(o0 * tanh_ap(c0a), o1 * tanh_ap(c0b));
                asm volatile("st.shared.b32 [%0], %1;"
                             :: "r"(h0st + (hp ^ 1) * HBUF), "r"(hv) : "memory");
            }
        }
        __syncthreads();                                  // bar1

        // ---- phaseB: preacts1 = h0[hp^1]@Wih1^T + h1[hp]@Whh1^T ; cell ----
        {
            float acc[4][4] = {{0,0,0,0},{0,0,0,0},{0,0,0,0},{0,0,0,0}};
#pragma unroll
            for (int kt = 0; kt < 4; kt++) {
                uint32_t a[4];
                ldsm_x4(a, h0base + (hp ^ 1) * HBUF + kt * 32);
#pragma unroll
                for (int nb2 = 0; nb2 < 4; nb2++)
                    mma_f16(acc[nb2], a, fw1[nb2][kt]);
            }
#pragma unroll
            for (int kt = 0; kt < 4; kt++) {
                uint32_t a[4];
                ldsm_x4(a, h1base + hp * HBUF + kt * 32);
#pragma unroll
                for (int nb2 = 0; nb2 < 4; nb2++)
                    mma_f16(acc[nb2], a, fw1[nb2][kt + 4]);
            }
            if (cellth) {
                float i0 = sig_ap(acc[0][0] + bq[0].x),
                      i1 = sig_ap(acc[0][1] + bq[0].y);
                float f0 = sig_ap(acc[1][0] + bq[1].x),
                      f1 = sig_ap(acc[1][1] + bq[1].y);
                float g0 = tanh_ap(acc[2][0] + bq[2].x),
                      g1 = tanh_ap(acc[2][1] + bq[2].y);
                float o0 = sig_ap(acc[3][0] + bq[3].x),
                      o1 = sig_ap(acc[3][1] + bq[3].y);
                c1a = f0 * c1a + i0 * g0;
                c1b = f1 * c1b + i1 * g1;
                hva = o0 * tanh_ap(c1a);
                hvb = o1 * tanh_ap(c1b);
                uint32_t hv = packh2(hva, hvb);
                asm volatile("st.shared.b32 [%0], %1;"
                             :: "r"(h1st + (hp ^ 1) * HBUF), "r"(hv) : "memory");
            }
        }
        __syncthreads();                                  // bar2

        if (cellth) {
#pragma unroll
            for (int q = 0; q < 4; q++) xq[q] = xn[q];
        }
        hp ^= 1;
    }

    // epilogue: final h1 (f32, exact) -> h1f, then FC
    if (cellth) {
        h1f[gid * 64 + j0] = hva;
        h1f[gid * 64 + j0 + 1] = hvb;
    }
    __syncthreads();

    if (tid < 2 * NB) {
        const int nb = tid >> 1, o = tid & 1;
        float s = bfc[o];
#pragma unroll
        for (int k = 0; k < HDIM; k++)
            s += Wfc[o * HDIM + k] * h1f[nb * HDIM + k];
        out[(b0i + nb) * 2 + o] = 1.0f / (1.0f + __expf(-s));
    }
}

// ================================ launcher =====================================
extern "C" void kernel_launch(void* const* d_in, const int* in_sizes, int n_in,
                              void* d_out, int out_size) {
    const int*   seq  = (const int*)d_in[0];
    const float* emb  = (const float*)d_in[1];
    const float* Wih0 = (const float*)d_in[2];
    const float* Whh0 = (const float*)d_in[3];
    const float* bih0 = (const float*)d_in[4];
    const float* bhh0 = (const float*)d_in[5];
    const float* Wih1 = (const float*)d_in[6];
    const float* Whh1 = (const float*)d_in[7];
    const float* bih1 = (const float*)d_in[8];
    const float* bhh1 = (const float*)d_in[9];
    const float* Wfc  = (const float*)d_in[10];
    const float* bfc  = (const float*)d_in[11];
    float* out = (float*)d_out;

    cudaFuncSetAttribute(embed_xproj_mma,
                         cudaFuncAttributeMaxDynamicSharedMemorySize, KM_SMEM);
    cudaFuncSetAttribute(lstm_rec_mma,
                         cudaFuncAttributeMaxDynamicSharedMemorySize, KBM_SMEM);

    embed_xproj_mma<<<148, 256, KM_SMEM>>>(seq, emb, Wih0, bih0, bhh0);
    lstm_rec_mma<<<BSZ / NB, 256, KBM_SMEM>>>(Whh0, Wih1, Whh1, bih1, bhh1,
                                              Wfc, bfc, out);
}

// round 11
// speedup vs baseline: 3.5189x; 1.1255x over previous
#include <cuda_runtime.h>
#include <cuda_fp16.h>
#include <cstdint>

#define EV 50000
#define EDIM 128
#define HDIM 64
#define GDIM 256
#define BSZ 512
#define SLEN 512
#define NB 4
typedef unsigned long long ull;

__device__ float g_xproj[(size_t)BSZ * SLEN * GDIM];

__device__ __forceinline__ uint32_t smem_u32(const void* p) {
    uint32_t a;
    asm("{ .reg .u64 t; cvta.to.shared.u64 t, %1; cvt.u32.u64 %0, t; }"
        : "=r"(a) : "l"(p));
    return a;
}
__device__ __forceinline__ float tanh_ap(float x) {
    float y; asm("tanh.approx.f32 %0, %1;" : "=f"(y) : "f"(x));
    return y;
}
__device__ __forceinline__ float sig_ap(float x) {
    return 0.5f * tanh_ap(0.5f * x) + 0.5f;
}
__device__ __forceinline__ void mma_f16(float* d, const uint32_t* a,
                                        const uint32_t* b) {
    asm volatile(
        "mma.sync.aligned.m16n8k16.row.col.f32.f16.f16.f32 "
        "{%0,%1,%2,%3}, {%4,%5,%6,%7}, {%8,%9}, {%0,%1,%2,%3};"
        : "+f"(d[0]), "+f"(d[1]), "+f"(d[2]), "+f"(d[3])
        : "r"(a[0]), "r"(a[1]), "r"(a[2]), "r"(a[3]), "r"(b[0]), "r"(b[1]));
}
__device__ __forceinline__ void ldsm_x4(uint32_t* r, uint32_t addr) {
    asm volatile(
        "ldmatrix.sync.aligned.m8n8.x4.shared.b16 {%0,%1,%2,%3}, [%4];"
        : "=r"(r[0]), "=r"(r[1]), "=r"(r[2]), "=r"(r[3]) : "r"(addr));
}
__device__ __forceinline__ uint32_t packh2(float lo, float hi) {
    __half2 h = __floats2half2_rn(lo, hi);
    return *(uint32_t*)&h;
}

// ============ Kernel A: embed + x@Wih0^T + bias via fp16 mma, reg weights ======
// Warp w owns gates [32w,32w+32). Wih0 fragments in 64 regs (loaded once).
// x tile: 64 tokens fp16 in smem [64][136] (272B rows -> conflict-free ldsm).
#define KH_PAD 136
#define KH_SMEM (64 * KH_PAD * 2 + 256 * 4)

__global__ void __launch_bounds__(256, 1)
embed_xproj_f16(const int* __restrict__ seq, const float* __restrict__ emb,
                const float* __restrict__ Wih0, const float* __restrict__ bih0,
                const float* __restrict__ bhh0) {
    extern __shared__ char smc[];
    __half* xh = (__half*)smc;                      // [64][136]
    float* bs = (float*)(smc + 64 * KH_PAD * 2);    // [256]

    const int tid = threadIdx.x;
    const int lane = tid & 31, w = tid >> 5;
    const int gid = lane >> 2, tig = lane & 3;
    const int nbase = w * 32;

    if (tid < 256) bs[tid] = bih0[tid] + bhh0[tid];

    // weight fragments: gate g = nbase + nb*8 + gid, K=128 in 8 chunks of 16
    uint32_t fw[4][8][2];
#pragma unroll
    for (int nb = 0; nb < 4; nb++) {
        const float* row = Wih0 + (nbase + nb * 8 + gid) * EDIM;
#pragma unroll
        for (int kt = 0; kt < 8; kt++) {
            const int k0 = kt * 16 + 2 * tig;
            fw[nb][kt][0] = packh2(__ldg(row + k0), __ldg(row + k0 + 1));
            fw[nb][kt][1] = packh2(__ldg(row + k0 + 8), __ldg(row + k0 + 9));
        }
    }

    // ldmatrix lane offset
    const int mi = lane >> 3, rr = lane & 7;
    const uint32_t aoff =
        (uint32_t)(((mi & 1) * 8 + rr) * (KH_PAD * 2) + (mi >> 1) * 16);
    const uint32_t xbase = smem_u32(xh) + aoff;

    // gather: thread -> token tid>>2, k-quarter (tid&3)*32
    const int mytok = tid >> 2, kq = tid & 3;
    const int ntiles = (BSZ * SLEN) / 64;   // 4096
    float4 pf[8];

    auto ldx = [&](int tile) {
        int idx = __ldg(seq + tile * 64 + mytok);
        idx = idx < 0 ? 0 : (idx >= EV ? EV - 1 : idx);
        const float4* er = (const float4*)emb + (size_t)idx * 32 + kq * 8;
#pragma unroll
        for (int i = 0; i < 8; i++) pf[i] = __ldg(er + i);
    };
    auto stx = [&]() {
#pragma unroll
        for (int i = 0; i < 8; i++) {
            uint2 u;
            u.x = packh2(pf[i].x, pf[i].y);
            u.y = packh2(pf[i].z, pf[i].w);
            *(uint2*)&xh[mytok * KH_PAD + kq * 32 + i * 4] = u;
        }
    };

    int tile = blockIdx.x;
    if (tile < ntiles) ldx(tile);
    __syncthreads();
    if (tile < ntiles) stx();
    __syncthreads();

    for (; tile < ntiles; tile += gridDim.x) {
        const int nxt = tile + gridDim.x;
        if (nxt < ntiles) ldx(nxt);

        float acc[4][4][4];
#pragma unroll
        for (int mb = 0; mb < 4; mb++)
#pragma unroll
            for (int nb = 0; nb < 4; nb++)
#pragma unroll
                for (int i = 0; i < 4; i++) acc[mb][nb][i] = 0.0f;

#pragma unroll
        for (int kt = 0; kt < 8; kt++) {
            uint32_t a[4][4];
#pragma unroll
            for (int mb = 0; mb < 4; mb++)
                ldsm_x4(a[mb], xbase + mb * 16 * (KH_PAD * 2) + kt * 32);
#pragma unroll
            for (int mb = 0; mb < 4; mb++)
#pragma unroll
                for (int nb = 0; nb < 4; nb++)
                    mma_f16(acc[mb][nb], a[mb], fw[nb][kt]);
        }

#pragma unroll
        for (int mb = 0; mb < 4; mb++) {
#pragma unroll
            for (int nb = 0; nb < 4; nb++) {
                const int token = tile * 64 + mb * 16 + gid;
                const int gate = nbase + nb * 8 + 2 * tig;
                float2 bia = *(float2*)&bs[gate];
                float2 v0 = {acc[mb][nb][0] + bia.x, acc[mb][nb][1] + bia.y};
                float2 v1 = {acc[mb][nb][2] + bia.x, acc[mb][nb][3] + bia.y};
                *(float2*)&g_xproj[(size_t)token * GDIM + gate] = v0;
                *(float2*)&g_xproj[(size_t)(token + 8) * GDIM + gate] = v1;
            }
        }
        __syncthreads();
        if (nxt < ntiles) stx();
        __syncthreads();
    }
}

// ============ Kernel B: tensor-core recurrence, 1 barrier/step =================
#define HROWB 144
#define HBUF  (16 * HROWB)
#define KBM_SMEM (4 * HBUF + 256 * 4)

__global__ void __launch_bounds__(256, 1)
lstm_rec_mma(const float* __restrict__ Whh0, const float* __restrict__ Wih1,
             const float* __restrict__ Whh1, const float* __restrict__ bih1,
             const float* __restrict__ bhh1, const float* __restrict__ Wfc,
             const float* __restrict__ bfc, float* __restrict__ out) {
    extern __shared__ char smc[];
    float* h1f = (float*)(smc + 4 * HBUF);

    const int tid = threadIdx.x;
    const int lane = tid & 31, w = tid >> 5;
    const int gid = lane >> 2, tig = lane & 3;
    const bool cellth = (gid < 4);
    const int j0 = w * 8 + 2 * tig;

    for (int i = tid; i < 2304; i += 256) ((uint32_t*)smc)[i] = 0;

    uint32_t fw0[4][4][2], fw1[4][8][2];
#pragma unroll
    for (int nb2 = 0; nb2 < 4; nb2++) {
        const int g = nb2 * 64 + w * 8 + gid;
        const float* r0 = Whh0 + g * 64;
        const float* rx = Wih1 + g * 64;
        const float* rh = Whh1 + g * 64;
#pragma unroll
        for (int kt = 0; kt < 4; kt++) {
            const int k0 = kt * 16 + 2 * tig;
            fw0[nb2][kt][0] = packh2(__ldg(r0 + k0), __ldg(r0 + k0 + 1));
            fw0[nb2][kt][1] = packh2(__ldg(r0 + k0 + 8), __ldg(r0 + k0 + 9));
            fw1[nb2][kt][0] = packh2(__ldg(rx + k0), __ldg(rx + k0 + 1));
            fw1[nb2][kt][1] = packh2(__ldg(rx + k0 + 8), __ldg(rx + k0 + 9));
            fw1[nb2][kt + 4][0] = packh2(__ldg(rh + k0), __ldg(rh + k0 + 1));
            fw1[nb2][kt + 4][1] = packh2(__ldg(rh + k0 + 8), __ldg(rh + k0 + 9));
        }
    }
    float2 bq[4];
#pragma unroll
    for (int q = 0; q < 4; q++) {
        const int g = q * 64 + j0;
        bq[q].x = __ldg(bih1 + g) + __ldg(bhh1 + g);
        bq[q].y = __ldg(bih1 + g + 1) + __ldg(bhh1 + g + 1);
    }

    const int mi = lane >> 3, rr = lane & 7;
    const uint32_t aoff =
        (uint32_t)(((mi & 1) * 8 + rr) * HROWB + ((mi >> 1) * 8) * 2);
    const uint32_t h0base = smem_u32(smc) + aoff;
    const uint32_t h1base = smem_u32(smc) + 2 * HBUF + aoff;
    const uint32_t h0st = smem_u32(smc) + gid * HROWB + j0 * 2;
    const uint32_t h1st = smem_u32(smc) + 2 * HBUF + gid * HROWB + j0 * 2;

    const int b0i = blockIdx.x * NB;
    const float* xr = g_xproj +
        (size_t)(b0i + (cellth ? gid : 0)) * SLEN * GDIM;

    float c0a = 0.f, c0b = 0.f, c1a = 0.f, c1b = 0.f;
    float hva = 0.f, hvb = 0.f;
    float2 xq[4];
    if (cellth) {
#pragma unroll
        for (int q = 0; q < 4; q++) xq[q] = *(const float2*)(xr + q * 64 + j0);
    }
    uint32_t hp = 0;
    __syncthreads();

    for (int t = 0; t < SLEN; t++) {
        float2 xn[4];
        if (cellth) {
            const size_t toff = (size_t)((t + 1 < SLEN) ? t + 1 : t) * GDIM;
#pragma unroll
            for (int q = 0; q < 4; q++)
                xn[q] = *(const float2*)(xr + toff + q * 64 + j0);
        }

        // ---- phaseA: preacts0 = h0[hp] @ Whh0^T ; cell in-register ----
        {
            float acc[4][4] = {{0,0,0,0},{0,0,0,0},{0,0,0,0},{0,0,0,0}};
#pragma unroll
            for (int kt = 0; kt < 4; kt++) {
                uint32_t a[4];
                ldsm_x4(a, h0base + hp * HBUF + kt * 32);
#pragma unroll
                for (int nb2 = 0; nb2 < 4; nb2++)
                    mma_f16(acc[nb2], a, fw0[nb2][kt]);
            }
            if (cellth) {
                float i0 = sig_ap(acc[0][0] + xq[0].x),
                      i1 = sig_ap(acc[0][1] + xq[0].y);
                float f0 = sig_ap(acc[1][0] + xq[1].x),
                      f1 = sig_ap(acc[1][1] + xq[1].y);
                float g0 = tanh_ap(acc[2][0] + xq[2].x),
                      g1 = tanh_ap(acc[2][1] + xq[2].y);
                float o0 = sig_ap(acc[3][0] + xq[3].x),
                      o1 = sig_ap(acc[3][1] + xq[3].y);
                c0a = f0 * c0a + i0 * g0;
                c0b = f1 * c0b + i1 * g1;
                uint32_t hv = packh2(o0 * tanh_ap(c0a), o1 * tanh_ap(c0b));
                asm volatile("st.shared.b32 [%0], %1;"
                             :: "r"(h0st + (hp ^ 1) * HBUF), "r"(hv) : "memory");
            }
        }
        __syncthreads();                // the ONLY barrier per step

        // ---- phaseB: preacts1 = h0[hp^1]@Wih1^T + h1[hp]@Whh1^T ; cell ----
        // (safe without trailing barrier: next phaseA touches only the h0
        //  buffers, whose readers/writers are separated by the barrier above)
        {
            float acc[4][4] = {{0,0,0,0},{0,0,0,0},{0,0,0,0},{0,0,0,0}};
#pragma unroll
            for (int kt = 0; kt < 4; kt++) {
                uint32_t a[4];
                ldsm_x4(a, h0base + (hp ^ 1) * HBUF + kt * 32);
#pragma unroll
                for (int nb2 = 0; nb2 < 4; nb2++)
                    mma_f16(acc[nb2], a, fw1[nb2][kt]);
            }
#pragma unroll
            for (int kt = 0; kt < 4; kt++) {
                uint32_t a[4];
                ldsm_x4(a, h1base + hp * HBUF + kt * 32);
#pragma unroll
                for (int nb2 = 0; nb2 < 4; nb2++)
                    mma_f16(acc[nb2], a, fw1[nb2][kt + 4]);
            }
            if (cellth) {
                float i0 = sig_ap(acc[0][0] + bq[0].x),
                      i1 = sig_ap(acc[0][1] + bq[0].y);
                float f0 = sig_ap(acc[1][0] + bq[1].x),
                      f1 = sig_ap(acc[1][1] + bq[1].y);
                float g0 = tanh_ap(acc[2][0] + bq[2].x),
                      g1 = tanh_ap(acc[2][1] + bq[2].y);
                float o0 = sig_ap(acc[3][0] + bq[3].x),
                      o1 = sig_ap(acc[3][1] + bq[3].y);
                c1a = f0 * c1a + i0 * g0;
                c1b = f1 * c1b + i1 * g1;
                hva = o0 * tanh_ap(c1a);
                hvb = o1 * tanh_ap(c1b);
                uint32_t hv = packh2(hva, hvb);
                asm volatile("st.shared.b32 [%0], %1;"
                             :: "r"(h1st + (hp ^ 1) * HBUF), "r"(hv) : "memory");
            }
        }

        if (cellth) {
#pragma unroll
            for (int q = 0; q < 4; q++) xq[q] = xn[q];
        }
        hp ^= 1;
    }

    if (cellth) {
        h1f[gid * 64 + j0] = hva;
        h1f[gid * 64 + j0 + 1] = hvb;
    }
    __syncthreads();

    if (tid < 2 * NB) {
        const int nb = tid >> 1, o = tid & 1;
        float s = bfc[o];
#pragma unroll
        for (int k = 0; k < HDIM; k++)
            s += Wfc[o * HDIM + k] * h1f[nb * HDIM + k];
        out[(b0i + nb) * 2 + o] = 1.0f / (1.0f + __expf(-s));
    }
}

// ================================ launcher =====================================
extern "C" void kernel_launch(void* const* d_in, const int* in_sizes, int n_in,
                              void* d_out, int out_size) {
    const int*   seq  = (const int*)d_in[0];
    const float* emb  = (const float*)d_in[1];
    const float* Wih0 = (const float*)d_in[2];
    const float* Whh0 = (const float*)d_in[3];
    const float* bih0 = (const float*)d_in[4];
    const float* bhh0 = (const float*)d_in[5];
    const float* Wih1 = (const float*)d_in[6];
    const float* Whh1 = (const float*)d_in[7];
    const float* bih1 = (const float*)d_in[8];
    const float* bhh1 = (const float*)d_in[9];
    const float* Wfc  = (const float*)d_in[10];
    const float* bfc  = (const float*)d_in[11];
    float* out = (float*)d_out;

    cudaFuncSetAttribute(embed_xproj_f16,
                         cudaFuncAttributeMaxDynamicSharedMemorySize, KH_SMEM);
    cudaFuncSetAttribute(lstm_rec_mma,
                         cudaFuncAttributeMaxDynamicSharedMemorySize, KBM_SMEM);

    embed_xproj_f16<<<148, 256, KH_SMEM>>>(seq, emb, Wih0, bih0, bhh0);
    lstm_rec_mma<<<BSZ / NB, 256, KBM_SMEM>>>(Whh0, Wih1, Whh1, bih1, bhh1,
                                              Wfc, bfc, out);
}